// round 8
// baseline (speedup 1.0000x reference)
#include <cuda_runtime.h>
#include <cuda_bf16.h>
#include <cstdint>

// Shapes (fixed by dataset):
//   messages (B=32, E=8192, D=128) fp32 | tgt (B=32, E=8192) int32
//   out      (B=32, N=2048, D=128) fp32
static constexpr int B = 32;
static constexpr int E = 8192;
static constexpr int N = 2048;
static constexpr int D = 128;                    // 512 B per row
static constexpr int TOTAL = B * E;              // 262144 rows
static constexpr int GRP = 8;                    // rows per warp-group
static constexpr int NGROUPS = TOTAL / GRP;      // 32768
static constexpr int OUT_F4 = B * N * D / 4;     // 2097152 float4

// Global-barrier state: monotonically increasing across graph replays, so no
// reset is ever needed (epoch = arrivals / gridDim).
__device__ unsigned g_arrive  = 0;
__device__ unsigned g_release = 0;

// Single fused kernel: zero + barrier + RED scatter.
//  - Grid is sized to EXACTLY the resident capacity (occupancy API) so the
//    software barrier cannot deadlock.
//  - First row-group loads are issued BEFORE the zero loop so the DRAM read
//    stream overlaps the (L2-bound) zero stores.
__global__ __launch_bounds__(256) void fused_scatter(
    const float4* __restrict__ messages,   // (TOTAL, 32) float4
    const int*    __restrict__ tgt,        // (TOTAL,)
    float4*       __restrict__ out4,       // (B*N*D/4,)
    int nblocks)
{
    const int tid      = threadIdx.x;
    const int lane     = tid & 31;
    const int gtid     = blockIdx.x * 256 + tid;
    const int nthreads = nblocks * 256;
    const int nwarps   = nthreads >> 5;
    const int warp     = gtid >> 5;

    // ── Phase A: front-issue the first group's loads (overlap with zeroing) ──
    const int g0 = warp;                       // first group for this warp
    float4 v[GRP];
    int t8 = 0;
    if (g0 < NGROUPS) {
        if (lane < GRP) t8 = __ldg(&tgt[g0 * GRP + lane]);
#pragma unroll
        for (int j = 0; j < GRP; j++)
            v[j] = __ldcs(&messages[(size_t)(g0 * GRP + j) * 32 + lane]);
    }

    // ── Phase B: zero the output (plain STG.128, grid-stride) ──
    const float4 z = make_float4(0.f, 0.f, 0.f, 0.f);
    for (int i = gtid; i < OUT_F4; i += nthreads)
        out4[i] = z;

    // ── Phase C: global barrier (epoch-based, replay-safe) ──
    __syncthreads();
    if (tid == 0) {
        __threadfence();                               // make zeros visible
        const unsigned a     = atomicAdd(&g_arrive, 1u);
        const unsigned epoch = a / (unsigned)nblocks;
        if (a % (unsigned)nblocks == (unsigned)nblocks - 1u) {
            __threadfence();
            atomicExch(&g_release, epoch + 1u);        // release the epoch
        } else {
            unsigned r;
            do {
                asm volatile("ld.global.acquire.gpu.u32 %0, [%1];"
                             : "=r"(r) : "l"(&g_release));
                if (r > epoch) break;
                __nanosleep(40);
            } while (true);
        }
    }
    __syncthreads();

    // ── Phase D: RED.128 scatter; first group already in registers ──
    float* out = (float*)out4;
    for (int g = g0; g < NGROUPS; g += nwarps) {
        if (g != g0) {
            if (lane < GRP) t8 = __ldg(&tgt[g * GRP + lane]);
#pragma unroll
            for (int j = 0; j < GRP; j++)
                v[j] = __ldcs(&messages[(size_t)(g * GRP + j) * 32 + lane]);
        }
#pragma unroll
        for (int j = 0; j < GRP; j++) {
            const int row = g * GRP + j;
            const int tr  = __shfl_sync(0xFFFFFFFFu, t8, j);
            const int b   = row >> 13;                 // row / E
            float* dst = out + ((size_t)(b * N + tr) * D) + lane * 4;
            asm volatile(
                "red.global.add.v4.f32 [%0], {%1, %2, %3, %4};"
                :: "l"(dst), "f"(v[j].x), "f"(v[j].y), "f"(v[j].z), "f"(v[j].w)
                : "memory");
        }
    }
}

extern "C" void kernel_launch(void* const* d_in, const int* in_sizes, int n_in,
                              void* d_out, int out_size)
{
    const float4* messages = (const float4*)d_in[0];
    const int*    tgt      = (const int*)d_in[1];

    // Size the grid to exactly the resident capacity (barrier safety) —
    // deterministic host queries, no allocations.
    int dev = 0;
    cudaGetDevice(&dev);
    int sm_count = 148;
    cudaDeviceGetAttribute(&sm_count, cudaDevAttrMultiProcessorCount, dev);
    int blocks_per_sm = 1;
    cudaOccupancyMaxActiveBlocksPerMultiprocessor(
        &blocks_per_sm, fused_scatter, 256, 0);
    const int nblocks = sm_count * blocks_per_sm;

    fused_scatter<<<nblocks, 256>>>(messages, tgt, (float4*)d_out, nblocks);
}

// round 9
// speedup vs baseline: 1.0621x; 1.0621x over previous
#include <cuda_runtime.h>
#include <cuda_bf16.h>
#include <cstdint>

// Shapes (fixed by dataset):
//   messages (B=32, E=8192, D=128) fp32 | tgt (B=32, E=8192) int32
//   out      (B=32, N=2048, D=128) fp32
static constexpr int B = 32;
static constexpr int E = 8192;
static constexpr int N = 2048;
static constexpr int D = 128;               // 32 float4 per row
static constexpr int ROWS = 4;              // rows per warp (R2 proven shape)
static constexpr int WARPS = 8;             // warps per block
static constexpr int OUT_F4 = B * N * D / 4;   // 2097152 float4

// ── Primary: zero the output. Fires the PDL trigger IMMEDIATELY so the
//    scatter grid launches and overlaps its load prologue with these stores.
__global__ __launch_bounds__(256) void zero_out(float4* __restrict__ out4)
{
    asm volatile("griddepcontrol.launch_dependents;" ::: "memory");
    const float4 z = make_float4(0.f, 0.f, 0.f, 0.f);
    const int stride = gridDim.x * 256;
    for (int i = blockIdx.x * 256 + threadIdx.x; i < OUT_F4; i += stride)
        out4[i] = z;
}

// ── Secondary (PDL): prologue loads run before the dependency wait; the
//    RED.128 atomics (which need zeroed memory) run after it.
__global__ __launch_bounds__(WARPS * 32) void scatter_add(
    const float4* __restrict__ messages,   // (B*E, 32) float4
    const int*    __restrict__ tgt,        // (B*E,)
    float*        __restrict__ out)        // (B*N*D,)
{
    const int warp = blockIdx.x * WARPS + (threadIdx.x >> 5);
    const int lane = threadIdx.x & 31;
    const int row0 = warp * ROWS;

    // Prologue (safe pre-wait: reads only inputs, no output access).
    int t = 0;
    if (lane < ROWS) t = __ldg(&tgt[row0 + lane]);

    float4 v[ROWS];
#pragma unroll
    for (int r = 0; r < ROWS; r++)
        v[r] = __ldcs(&messages[(size_t)(row0 + r) * 32 + lane]);

    // Wait for the zero kernel to fully complete (memory visible).
    asm volatile("griddepcontrol.wait;" ::: "memory");

#pragma unroll
    for (int r = 0; r < ROWS; r++) {
        const int tr = __shfl_sync(0xFFFFFFFFu, t, r);
        const int b  = (row0 + r) >> 13;               // row / E
        float* dst = out + ((size_t)(b * N + tr) * D) + lane * 4;
        asm volatile(
            "red.global.add.v4.f32 [%0], {%1, %2, %3, %4};"
            :: "l"(dst), "f"(v[r].x), "f"(v[r].y), "f"(v[r].z), "f"(v[r].w)
            : "memory");
    }
}

extern "C" void kernel_launch(void* const* d_in, const int* in_sizes, int n_in,
                              void* d_out, int out_size)
{
    const float4* messages = (const float4*)d_in[0];
    const int*    tgt      = (const int*)d_in[1];

    // Primary: zero kernel (plain launch).
    zero_out<<<592, 256>>>((float4*)d_out);   // 4 blocks/SM-ish; grid-stride

    // Secondary: scatter with programmatic dependent launch.
    cudaLaunchConfig_t cfg = {};
    const int total_rows = B * E;                       // 262144
    cfg.gridDim  = dim3(total_rows / (WARPS * ROWS));   // 8192 (R2 shape)
    cfg.blockDim = dim3(WARPS * 32);
    cfg.dynamicSmemBytes = 0;
    cfg.stream = 0;
    cudaLaunchAttribute attr[1];
    attr[0].id = cudaLaunchAttributeProgrammaticStreamSerialization;
    attr[0].val.programmaticStreamSerializationAllowed = 1;
    cfg.attrs = attr;
    cfg.numAttrs = 1;
    cudaLaunchKernelEx(&cfg, scatter_add, messages, tgt, (float*)d_out);
}